// round 7
// baseline (speedup 1.0000x reference)
#include <cuda_runtime.h>
#include <cuda_bf16.h>
#include <cstdint>

#define D 128
#define MAX_NODES 100000

// Scratch for side_embeddings (SpMM result). __device__ global (no allocs allowed).
// float4 type guarantees 16B alignment for vector reductions/loads.
__device__ float4 g_side4[MAX_NODES * (D / 4)];   // 51.2 MB

// Flag: 1 if edge_index buffer is int32, 0 if int64. Set by detect kernel.
__device__ int g_idx_is32;

// ---------------------------------------------------------------------------
// Kernel 0: detect edge_index dtype on-device (graph-safe, no host readback).
// Under an int32 layout, an int64-read's high word is a random node index
// (< 100000), zero with p=1e-5; 64 samples all-zero => genuinely int64.
// ---------------------------------------------------------------------------
__global__ void detect_idx_dtype_kernel(const unsigned long long* __restrict__ ei,
                                        int n_samples) {
    if (blockIdx.x == 0 && threadIdx.x == 0) {
        int is32 = 1;
        for (int i = 0; i < n_samples; i++) {
            if (ei[i] >> 32) { is32 = 0; break; }   // high bits set -> NOT int32 pairs... 
        }
        // NOTE: logic: if dtype is int64, all values < 1e5 -> high word always 0.
        // If dtype is int32, the high word is a random index, almost surely
        // nonzero for at least one of 64 samples. So: any nonzero high word
        // => int32 layout.
        int saw_high = 0;
        for (int i = 0; i < n_samples; i++) {
            if (ei[i] >> 32) { saw_high = 1; break; }
        }
        is32 = saw_high;
        g_idx_is32 = is32;
    }
}

// ---------------------------------------------------------------------------
// Kernel 1: zero the scratch accumulator
// ---------------------------------------------------------------------------
__global__ void zero_side_kernel(int n4) {
    int i = blockIdx.x * blockDim.x + threadIdx.x;
    if (i < n4) g_side4[i] = make_float4(0.f, 0.f, 0.f, 0.f);
}

// ---------------------------------------------------------------------------
// Kernel 2: edge scatter.  One warp per edge.
//   side[dst] += ego[src] * w      (128 floats = 32 float4, one per lane)
// Uses red.global.add.v4.f32 (no-return vector reduction, sm_90+).
// ---------------------------------------------------------------------------
__global__ void scatter_kernel(const float4* __restrict__ ego4,
                               const long long* __restrict__ edge_index,
                               const float* __restrict__ edge_weight,
                               int n_edges, int n_nodes) {
    int warp = (blockIdx.x * blockDim.x + threadIdx.x) >> 5;
    int lane = threadIdx.x & 31;
    if (warp >= n_edges) return;

    long long dst, src;
    if (g_idx_is32) {
        const int* e32 = (const int*)edge_index;
        dst = e32[warp];
        src = e32[n_edges + warp];
    } else {
        dst = edge_index[warp];              // row 0 = dst
        src = edge_index[n_edges + warp];    // row 1 = src
    }
    // Safety guard: drop out-of-range edges instead of faulting.
    if ((unsigned long long)dst >= (unsigned long long)n_nodes ||
        (unsigned long long)src >= (unsigned long long)n_nodes) return;

    float w = edge_weight[warp];

    float4 v = ego4[src * (D / 4) + lane];
    v.x *= w; v.y *= w; v.z *= w; v.w *= w;

    float4* p = &g_side4[dst * (D / 4) + lane];
    asm volatile("red.global.add.v4.f32 [%0], {%1, %2, %3, %4};"
                 :: "l"(p), "f"(v.x), "f"(v.y), "f"(v.z), "f"(v.w)
                 : "memory");
}

// ---------------------------------------------------------------------------
// Kernel 3: out = LeakyReLU((ego + side) @ W^T + b)
// Block: 256 threads, BM=64 rows, BN=128 cols (full D).
// Per-thread 8x4 register microtile. W^T staged in smem with pad-132 rows
// (odd float4 stride -> conflict-free vectorized reads).
// ---------------------------------------------------------------------------
#define WS_STRIDE 132   // 128 + 4 pad (keeps 16B alignment, shifts banks per row)

__global__ __launch_bounds__(256, 2)
void gemm_lrelu_kernel(const float* __restrict__ ego,
                       const float* __restrict__ W,
                       const float* __restrict__ b,
                       float* __restrict__ out,
                       int n_nodes) {
    extern __shared__ float sm[];
    float* Ws = sm;                       // [128][WS_STRIDE]  (Ws[k][j] = W[j][k])
    float* xs = Ws + D * WS_STRIDE;       // [64][128]
    float* bs = xs + 64 * D;              // [128]

    const float* side = reinterpret_cast<const float*>(g_side4);
    int tid = threadIdx.x;

    // Stage W transposed. Global read coalesced; smem write stride 132 -> conflict-free.
    for (int idx = tid; idx < D * D; idx += 256) {
        int j = idx >> 7;          // row of W
        int k = idx & (D - 1);     // col of W
        Ws[k * WS_STRIDE + j] = W[idx];
    }
    if (tid < D) bs[tid] = b[tid];

    int row0 = blockIdx.x * 64;

    // Stage x tile = ego + side  (coalesced reads, linear smem writes)
    for (int idx = tid; idx < 64 * D; idx += 256) {
        int r = idx >> 7;
        int row = row0 + r;
        xs[idx] = (row < n_nodes) ? (ego[row * D + (idx & (D - 1))] +
                                     side[row * D + (idx & (D - 1))]) : 0.f;
    }
    __syncthreads();

    int cg = tid & 31;    // column group: 4 cols each, lanes contiguous -> coalesced stores
    int rg = tid >> 5;    // row group: 8 rows each

    float acc[8][4];
    float4 bv = *reinterpret_cast<const float4*>(bs + cg * 4);
    #pragma unroll
    for (int r = 0; r < 8; r++) {
        acc[r][0] = bv.x; acc[r][1] = bv.y; acc[r][2] = bv.z; acc[r][3] = bv.w;
    }

    const float* xb = xs + (rg * 8) * D;

    #pragma unroll 4
    for (int k = 0; k < D; k++) {
        float4 wv = *reinterpret_cast<const float4*>(Ws + k * WS_STRIDE + cg * 4);
        #pragma unroll
        for (int r = 0; r < 8; r++) {
            float xv = xb[r * D + k];   // broadcast across warp (same addr all lanes)
            acc[r][0] += xv * wv.x;
            acc[r][1] += xv * wv.y;
            acc[r][2] += xv * wv.z;
            acc[r][3] += xv * wv.w;
        }
    }

    // Epilogue: LeakyReLU(0.01) + coalesced float4 stores
    #pragma unroll
    for (int r = 0; r < 8; r++) {
        int row = row0 + rg * 8 + r;
        if (row < n_nodes) {
            float4 o;
            o.x = acc[r][0] > 0.f ? acc[r][0] : 0.01f * acc[r][0];
            o.y = acc[r][1] > 0.f ? acc[r][1] : 0.01f * acc[r][1];
            o.z = acc[r][2] > 0.f ? acc[r][2] : 0.01f * acc[r][2];
            o.w = acc[r][3] > 0.f ? acc[r][3] : 0.01f * acc[r][3];
            *reinterpret_cast<float4*>(out + row * D + cg * 4) = o;
        }
    }
}

// ---------------------------------------------------------------------------
// Launch
// Inputs (metadata order): ego_embeddings [N,128] f32, edge_index [2,E] i64/i32,
//                          edge_weight [E] f32, W [128,128] f32, b [128] f32
// Output: [N,128] f32
// ---------------------------------------------------------------------------
extern "C" void kernel_launch(void* const* d_in, const int* in_sizes, int n_in,
                              void* d_out, int out_size) {
    const float*     ego = (const float*)d_in[0];
    const long long* ei  = (const long long*)d_in[1];
    const float*     ew  = (const float*)d_in[2];
    const float*     W   = (const float*)d_in[3];
    const float*     b   = (const float*)d_in[4];
    float*           out = (float*)d_out;

    int n_nodes = in_sizes[0] / D;
    int n_edges = in_sizes[2];

    // 0) detect edge_index dtype (int32 vs int64) on-device
    int n_samples = n_edges < 64 ? n_edges : 64;
    detect_idx_dtype_kernel<<<1, 32>>>((const unsigned long long*)ei, n_samples);

    // 1) zero scratch
    int n4 = n_nodes * (D / 4);
    zero_side_kernel<<<(n4 + 255) / 256, 256>>>(n4);

    // 2) scatter: one warp per edge, 8 edges per 256-thread block
    int blocks = (n_edges + 7) / 8;
    scatter_kernel<<<blocks, 256>>>((const float4*)ego, ei, ew, n_edges, n_nodes);

    // 3) fused GEMM + bias + LeakyReLU
    size_t smem = (D * WS_STRIDE + 64 * D + D) * sizeof(float);  // ~99 KB
    cudaFuncSetAttribute(gemm_lrelu_kernel,
                         cudaFuncAttributeMaxDynamicSharedMemorySize, (int)smem);
    int gblocks = (n_nodes + 63) / 64;
    gemm_lrelu_kernel<<<gblocks, 256, smem>>>(ego, W, b, out, n_nodes);
}

// round 8
// speedup vs baseline: 1.6069x; 1.6069x over previous
#include <cuda_runtime.h>
#include <cuda_bf16.h>
#include <cstdint>

#define D 128
#define MAX_NODES 100000
#define MAX_EDGES 1600000

// ---- scratch (__device__ globals; no allocs allowed) ----
__device__ float4 g_x4[MAX_NODES * (D / 4)];     // x = ego + side, 51.2 MB
__device__ uint2  g_edges[MAX_EDGES];            // per-node sorted {src, w-bits}, 12.8 MB
__device__ int    g_counts[MAX_NODES];
__device__ int    g_offsets[MAX_NODES];
__device__ int    g_cursor[MAX_NODES];
__device__ int    g_total;
__device__ int    g_idx_is32;

// ---------------------------------------------------------------------------
// K0: detect edge_index dtype. int64 indices < 1e5 -> high word always 0.
// int32 layout -> an int64-read's high word is a random index, ~surely nonzero
// in 64 samples. Any nonzero high word => int32.
// ---------------------------------------------------------------------------
__global__ void detect_idx_dtype_kernel(const unsigned long long* __restrict__ ei,
                                        int n_samples) {
    if (threadIdx.x == 0) {
        int saw_high = 0;
        for (int i = 0; i < n_samples; i++)
            if (ei[i] >> 32) { saw_high = 1; break; }
        g_idx_is32 = saw_high;
    }
}

// K1: zero counts + total
__global__ void zero_counts_kernel(int n_nodes) {
    int i = blockIdx.x * blockDim.x + threadIdx.x;
    if (i < n_nodes) g_counts[i] = 0;
    if (i == 0) g_total = 0;
}

// K2: histogram of dst degrees
__global__ void count_kernel(const void* __restrict__ ei, int n_edges, int n_nodes) {
    int e = blockIdx.x * blockDim.x + threadIdx.x;
    if (e >= n_edges) return;
    long long dst = g_idx_is32 ? (long long)((const int*)ei)[e]
                               : ((const long long*)ei)[e];
    if ((unsigned long long)dst < (unsigned long long)n_nodes)
        atomicAdd(&g_counts[dst], 1);
}

// K3: per-node segment offsets. Block-local exclusive scan (1024 elems) +
// one global atomicAdd per block for the base. Segments are disjoint; global
// order across blocks is irrelevant for correctness.
__global__ void offsets_kernel(int n_nodes) {
    __shared__ int warp_sums[32];
    __shared__ int block_base;
    int i = blockIdx.x * 1024 + threadIdx.x;
    int lane = threadIdx.x & 31, wid = threadIdx.x >> 5;

    int c = (i < n_nodes) ? g_counts[i] : 0;
    int x = c;
    #pragma unroll
    for (int d = 1; d < 32; d <<= 1) {
        int y = __shfl_up_sync(0xFFFFFFFFu, x, d);
        if (lane >= d) x += y;
    }
    if (lane == 31) warp_sums[wid] = x;
    __syncthreads();
    if (wid == 0) {
        int s = warp_sums[lane];
        #pragma unroll
        for (int d = 1; d < 32; d <<= 1) {
            int y = __shfl_up_sync(0xFFFFFFFFu, s, d);
            if (lane >= d) s += y;
        }
        warp_sums[lane] = s;
        if (lane == 31) block_base = atomicAdd(&g_total, s);
    }
    __syncthreads();
    int warp_base = (wid > 0) ? warp_sums[wid - 1] : 0;
    int excl = block_base + warp_base + (x - c);
    if (i < n_nodes) { g_offsets[i] = excl; g_cursor[i] = excl; }
}

// K4: scatter edges into per-node segments
__global__ void fill_kernel(const void* __restrict__ ei,
                            const float* __restrict__ ew,
                            int n_edges, int n_nodes) {
    int e = blockIdx.x * blockDim.x + threadIdx.x;
    if (e >= n_edges) return;
    long long dst, src;
    if (g_idx_is32) {
        dst = (long long)((const int*)ei)[e];
        src = (long long)((const int*)ei)[n_edges + e];
    } else {
        dst = ((const long long*)ei)[e];
        src = ((const long long*)ei)[n_edges + e];
    }
    if ((unsigned long long)dst >= (unsigned long long)n_nodes ||
        (unsigned long long)src >= (unsigned long long)n_nodes) return;
    int pos = atomicAdd(&g_cursor[dst], 1);
    if (pos < MAX_EDGES)
        g_edges[pos] = make_uint2((unsigned)src, __float_as_uint(ew[e]));
}

// K5: gather-aggregate. One warp per node:
//   x[v] = ego[v] + sum_e w_e * ego[src_e]     (128 floats = 32 float4/lane)
// Unroll-4 over edges for MLP on the random 512B row gathers.
__global__ __launch_bounds__(256)
void aggregate_kernel(const float4* __restrict__ ego4, int n_nodes) {
    int warp = (blockIdx.x * blockDim.x + threadIdx.x) >> 5;
    int lane = threadIdx.x & 31;
    if (warp >= n_nodes) return;

    int off = g_offsets[warp];
    int deg = g_counts[warp];

    float4 acc = ego4[(long)warp * (D / 4) + lane];

    int e = 0;
    for (; e + 4 <= deg; e += 4) {
        uint2 p0 = g_edges[off + e + 0];
        uint2 p1 = g_edges[off + e + 1];
        uint2 p2 = g_edges[off + e + 2];
        uint2 p3 = g_edges[off + e + 3];
        float4 r0 = ego4[(long)p0.x * (D / 4) + lane];
        float4 r1 = ego4[(long)p1.x * (D / 4) + lane];
        float4 r2 = ego4[(long)p2.x * (D / 4) + lane];
        float4 r3 = ego4[(long)p3.x * (D / 4) + lane];
        float w0 = __uint_as_float(p0.y), w1 = __uint_as_float(p1.y);
        float w2 = __uint_as_float(p2.y), w3 = __uint_as_float(p3.y);
        acc.x += r0.x * w0 + r1.x * w1 + r2.x * w2 + r3.x * w3;
        acc.y += r0.y * w0 + r1.y * w1 + r2.y * w2 + r3.y * w3;
        acc.z += r0.z * w0 + r1.z * w1 + r2.z * w2 + r3.z * w3;
        acc.w += r0.w * w0 + r1.w * w1 + r2.w * w2 + r3.w * w3;
    }
    for (; e < deg; e++) {
        uint2 p = g_edges[off + e];
        float4 r = ego4[(long)p.x * (D / 4) + lane];
        float w = __uint_as_float(p.y);
        acc.x += r.x * w; acc.y += r.y * w; acc.z += r.z * w; acc.w += r.w * w;
    }
    g_x4[(long)warp * (D / 4) + lane] = acc;
}

// ---------------------------------------------------------------------------
// K6: out = LeakyReLU(x @ W^T + b). Unchanged structure; reads precomputed x.
// ---------------------------------------------------------------------------
#define WS_STRIDE 132   // 128 + 4 pad: odd float4 stride -> conflict-free

__global__ __launch_bounds__(256, 2)
void gemm_lrelu_kernel(const float* __restrict__ W,
                       const float* __restrict__ b,
                       float* __restrict__ out,
                       int n_nodes) {
    extern __shared__ float sm[];
    float* Ws = sm;                       // [128][WS_STRIDE]  Ws[k][j] = W[j][k]
    float* xs = Ws + D * WS_STRIDE;       // [64][128]
    float* bs = xs + 64 * D;              // [128]

    const float* x = reinterpret_cast<const float*>(g_x4);
    int tid = threadIdx.x;

    for (int idx = tid; idx < D * D; idx += 256) {
        int j = idx >> 7;
        int k = idx & (D - 1);
        Ws[k * WS_STRIDE + j] = W[idx];
    }
    if (tid < D) bs[tid] = b[tid];

    int row0 = blockIdx.x * 64;
    for (int idx = tid; idx < 64 * D; idx += 256) {
        int row = row0 + (idx >> 7);
        xs[idx] = (row < n_nodes) ? x[(long)row * D + (idx & (D - 1))] : 0.f;
    }
    __syncthreads();

    int cg = tid & 31;
    int rg = tid >> 5;

    float acc[8][4];
    float4 bv = *reinterpret_cast<const float4*>(bs + cg * 4);
    #pragma unroll
    for (int r = 0; r < 8; r++) {
        acc[r][0] = bv.x; acc[r][1] = bv.y; acc[r][2] = bv.z; acc[r][3] = bv.w;
    }

    const float* xb = xs + (rg * 8) * D;

    #pragma unroll 4
    for (int k = 0; k < D; k++) {
        float4 wv = *reinterpret_cast<const float4*>(Ws + k * WS_STRIDE + cg * 4);
        #pragma unroll
        for (int r = 0; r < 8; r++) {
            float xv = xb[r * D + k];
            acc[r][0] += xv * wv.x;
            acc[r][1] += xv * wv.y;
            acc[r][2] += xv * wv.z;
            acc[r][3] += xv * wv.w;
        }
    }

    #pragma unroll
    for (int r = 0; r < 8; r++) {
        int row = row0 + rg * 8 + r;
        if (row < n_nodes) {
            float4 o;
            o.x = acc[r][0] > 0.f ? acc[r][0] : 0.01f * acc[r][0];
            o.y = acc[r][1] > 0.f ? acc[r][1] : 0.01f * acc[r][1];
            o.z = acc[r][2] > 0.f ? acc[r][2] : 0.01f * acc[r][2];
            o.w = acc[r][3] > 0.f ? acc[r][3] : 0.01f * acc[r][3];
            *reinterpret_cast<float4*>(out + (long)row * D + cg * 4) = o;
        }
    }
}

// ---------------------------------------------------------------------------
extern "C" void kernel_launch(void* const* d_in, const int* in_sizes, int n_in,
                              void* d_out, int out_size) {
    const float* ego = (const float*)d_in[0];
    const void*  ei  = d_in[1];
    const float* ew  = (const float*)d_in[2];
    const float* W   = (const float*)d_in[3];
    const float* b   = (const float*)d_in[4];
    float*       out = (float*)d_out;

    int n_nodes = in_sizes[0] / D;
    int n_edges = in_sizes[2];
    if (n_edges > MAX_EDGES) n_edges = MAX_EDGES;

    int n_samples = n_edges < 64 ? n_edges : 64;
    detect_idx_dtype_kernel<<<1, 32>>>((const unsigned long long*)ei, n_samples);

    zero_counts_kernel<<<(n_nodes + 255) / 256, 256>>>(n_nodes);
    count_kernel<<<(n_edges + 255) / 256, 256>>>(ei, n_edges, n_nodes);
    offsets_kernel<<<(n_nodes + 1023) / 1024, 1024>>>(n_nodes);
    fill_kernel<<<(n_edges + 255) / 256, 256>>>(ei, ew, n_edges, n_nodes);

    // aggregate: warp per node, 8 warps per block
    aggregate_kernel<<<(n_nodes + 7) / 8, 256>>>((const float4*)ego, n_nodes);

    size_t smem = (D * WS_STRIDE + 64 * D + D) * sizeof(float);
    cudaFuncSetAttribute(gemm_lrelu_kernel,
                         cudaFuncAttributeMaxDynamicSharedMemorySize, (int)smem);
    gemm_lrelu_kernel<<<(n_nodes + 63) / 64, 256, smem>>>(W, b, out, n_nodes);
}